// round 4
// baseline (speedup 1.0000x reference)
#include <cuda_runtime.h>
#include <cuda_bf16.h>
#include <cstdint>

#define NPIX   32768      // 8*64*64 pixels
#define DDIM   512
#define NKEYS  2000
#define MKEYS  2048       // padded key count

// ---------------- scratch (static device arrays; no allocation allowed) ----
__device__ __align__(256) __nv_bfloat16 g_qb[(size_t)NPIX * DDIM];   // 32 MB normalized q, bf16
__device__ __align__(256) __nv_bfloat16 g_kb[(size_t)MKEYS * DDIM];  // 2 MB keys, bf16
__device__ __align__(256) float g_kq[MKEYS];                         // |k|^2 (pad = 3e38)
__device__ __align__(256) float g_rnorm[NPIX];                       // 1/max(|q|,eps)
__device__ __align__(256) int   g_cand[(size_t)NPIX * 8];            // 8 candidates / pixel

// =================== kernel 1: key prep ===================
__global__ void prep_keys_k(const float* __restrict__ keys) {
    int j = blockIdx.x;          // 0..MKEYS-1
    int t = threadIdx.x;         // 128 threads
    float s = 0.f;
    if (j < NKEYS) {
        float4 v = ((const float4*)(keys + (size_t)j * DDIM))[t];
        s = v.x*v.x + v.y*v.y + v.z*v.z + v.w*v.w;
        __nv_bfloat162* dst = (__nv_bfloat162*)(g_kb + (size_t)j * DDIM);
        dst[2*t+0] = __floats2bfloat162_rn(v.x, v.y);
        dst[2*t+1] = __floats2bfloat162_rn(v.z, v.w);
    } else {
        ((float2*)(g_kb + (size_t)j * DDIM))[t] = make_float2(0.f, 0.f);
    }
    #pragma unroll
    for (int o = 16; o; o >>= 1) s += __shfl_xor_sync(0xffffffffu, s, o);
    __shared__ float ws[4];
    if ((t & 31) == 0) ws[t >> 5] = s;
    __syncthreads();
    if (t == 0) g_kq[j] = (j < NKEYS) ? (ws[0] + ws[1] + ws[2] + ws[3]) : 3.0e38f;
}

// =================== kernel 2: normalize + transpose ===================
// one CTA per (b,h): 64 pixels x 512 channels staged in 128KB smem
__global__ void __launch_bounds__(256) normalize_k(const float* __restrict__ query) {
    extern __shared__ float tile[];            // [512][68]  (stride 68 floats)
    __shared__ float part[16][16][4];
    __shared__ float rnw[64];

    int bh = blockIdx.x;                       // 0..511  (= b*64 + h)
    int b = bh >> 6, h = bh & 63;
    const float* base = query + (size_t)b * (512 * 4096) + (size_t)h * 64;
    int t = threadIdx.x;

    float a0 = 0.f, a1 = 0.f, a2 = 0.f, a3 = 0.f;
    #pragma unroll
    for (int i = 0; i < 32; i++) {
        int idx = t + i * 256;                 // 8192 float4s
        int c = idx >> 4, w4 = idx & 15;       // w4 fixed per thread (t & 15)
        float4 v = *(const float4*)(base + (size_t)c * 4096 + w4 * 4);
        *(float4*)(tile + c * 68 + w4 * 4) = v;
        a0 = fmaf(v.x, v.x, a0); a1 = fmaf(v.y, v.y, a1);
        a2 = fmaf(v.z, v.z, a2); a3 = fmaf(v.w, v.w, a3);
    }
    part[t & 15][t >> 4][0] = a0; part[t & 15][t >> 4][1] = a1;
    part[t & 15][t >> 4][2] = a2; part[t & 15][t >> 4][3] = a3;
    __syncthreads();
    if (t < 64) {                              // deterministic norm reduction
        float s = 0.f;
        #pragma unroll
        for (int m = 0; m < 16; m++) s += part[t >> 2][m][t & 3];
        float rn = 1.f / fmaxf(sqrtf(s), 1e-12f);
        rnw[t] = rn;
        g_rnorm[bh * 64 + t] = rn;
    }
    __syncthreads();

    int lane = t & 31, warp = t >> 5;
    #pragma unroll
    for (int it = 0; it < 8; it++) {
        int w = warp * 8 + it;
        float rn = rnw[w];
        __nv_bfloat162* dst = (__nv_bfloat162*)(g_qb + (size_t)(bh * 64 + w) * DDIM);
        #pragma unroll
        for (int j = 0; j < 8; j++) {
            int c = j * 64 + lane * 2;
            float x = tile[c * 68 + w] * rn;
            float y = tile[(c + 1) * 68 + w] * rn;
            dst[j * 32 + lane] = __floats2bfloat162_rn(x, y);
        }
    }
}

// =================== kernel 3: bf16 GEMM + fused top-4 ===================
// CTA: 256 thr, tile = 128 pixels x (all 2048 keys in 16 tiles of 128), K=512
// smem: A full [128][520]h (130KB) + B chunk [128][72]h (18KB) + scores [128][129]f (66KB)
#define A_BYTES (128 * 520 * 2)
#define B_BYTES (128 * 72 * 2)
#define S_BYTES (128 * 129 * 4)
#define G_SMEM  (A_BYTES + B_BYTES + S_BYTES)

__global__ void __launch_bounds__(256, 1) gemm_topk_k() {
    extern __shared__ unsigned char smem[];
    __nv_bfloat16* As = (__nv_bfloat16*)smem;                  // [128][520]
    __nv_bfloat16* Bs = (__nv_bfloat16*)(smem + A_BYTES);      // [128][72]
    float*         Ss = (float*)(smem + A_BYTES + B_BYTES);    // [128][129]

    int t = threadIdx.x, lane = t & 31, warp = t >> 5;
    int p0 = blockIdx.x * 128;

    // load full A tile (128x512 bf16), row stride 520 halves (=65 uint4)
    {
        const uint4* src = (const uint4*)(g_qb + (size_t)p0 * DDIM);
        uint4* dst = (uint4*)As;
        #pragma unroll
        for (int i = 0; i < 32; i++) {
            int idx = t + i * 256;
            int r = idx >> 6, c = idx & 63;
            dst[r * 65 + c] = src[r * 64 + c];
        }
    }

    float ts0 = 1e30f, ts1 = 1e30f, ts2 = 1e30f, ts3 = 1e30f;
    int   ti0 = 0, ti1 = 0, ti2 = 0, ti3 = 0;

    int wm = warp >> 1, wn = warp & 1;     // 4x2 warp grid, warp tile 32(M)x64(N)
    int ar = wm * 32 + (lane >> 2);
    int ac = (lane & 3) * 2;
    int br = wn * 64 + (lane >> 2);
    int bc = (lane & 3) * 2;
    int pr = t & 127;                      // scan: pixel row
    int ch = t >> 7;                       // scan: column half (0/1)

    for (int tile = 0; tile < 16; tile++) {
        float acc[2][8][4];
        #pragma unroll
        for (int mt = 0; mt < 2; mt++)
            #pragma unroll
            for (int nt = 0; nt < 8; nt++)
                #pragma unroll
                for (int k = 0; k < 4; k++) acc[mt][nt][k] = 0.f;

        #pragma unroll 1
        for (int kc = 0; kc < 8; kc++) {   // K chunks of 64
            __syncthreads();               // B buffer free (also covers A fill on 1st pass)
            {
                const uint4* src = (const uint4*)g_kb;
                uint4* dst = (uint4*)Bs;
                #pragma unroll
                for (int i = 0; i < 4; i++) {
                    int idx = t + i * 256;
                    int r = idx >> 3, c = idx & 7;
                    dst[r * 9 + c] = src[(size_t)(tile * 128 + r) * 64 + kc * 8 + c];
                }
            }
            __syncthreads();
            #pragma unroll
            for (int ks = 0; ks < 4; ks++) {
                unsigned a[2][4];
                #pragma unroll
                for (int mt = 0; mt < 2; mt++) {
                    int base = (ar + mt * 16) * 520 + kc * 64 + ks * 16 + ac;
                    a[mt][0] = *(const unsigned*)(As + base);
                    a[mt][1] = *(const unsigned*)(As + base + 8 * 520);
                    a[mt][2] = *(const unsigned*)(As + base + 8);
                    a[mt][3] = *(const unsigned*)(As + base + 8 * 520 + 8);
                }
                #pragma unroll
                for (int nt = 0; nt < 8; nt++) {
                    int bb = (br + nt * 8) * 72 + ks * 16 + bc;
                    unsigned b0 = *(const unsigned*)(Bs + bb);
                    unsigned b1 = *(const unsigned*)(Bs + bb + 8);
                    #pragma unroll
                    for (int mt = 0; mt < 2; mt++) {
                        asm volatile(
                            "mma.sync.aligned.m16n8k16.row.col.f32.bf16.bf16.f32 "
                            "{%0,%1,%2,%3}, {%4,%5,%6,%7}, {%8,%9}, {%0,%1,%2,%3};\n"
                            : "+f"(acc[mt][nt][0]), "+f"(acc[mt][nt][1]),
                              "+f"(acc[mt][nt][2]), "+f"(acc[mt][nt][3])
                            : "r"(a[mt][0]), "r"(a[mt][1]), "r"(a[mt][2]), "r"(a[mt][3]),
                              "r"(b0), "r"(b1));
                    }
                }
            }
        }
        // stage dot-products to smem (safe: all threads passed >=1 barrier since last scan)
        #pragma unroll
        for (int mt = 0; mt < 2; mt++)
            #pragma unroll
            for (int nt = 0; nt < 8; nt++) {
                int r = wm * 32 + mt * 16 + (lane >> 2);
                int c = wn * 64 + nt * 8 + (lane & 3) * 2;
                Ss[r * 129 + c]           = acc[mt][nt][0];
                Ss[r * 129 + c + 1]       = acc[mt][nt][1];
                Ss[(r + 8) * 129 + c]     = acc[mt][nt][2];
                Ss[(r + 8) * 129 + c + 1] = acc[mt][nt][3];
            }
        __syncthreads();
        // per-pixel top-4 scan: thread pr scans its column half (64 keys)
        int kb = tile * 128 + ch * 64;
        #pragma unroll 4
        for (int c = 0; c < 64; c++) {
            float dot = Ss[pr * 129 + ch * 64 + c];
            float sc = g_kq[kb + c] - 2.f * dot;   // |k|^2 - 2 q.k  (argmin-equiv)
            int idx = kb + c;
            if (sc < ts3) {
                if (sc < ts2) {
                    ts3 = ts2; ti3 = ti2;
                    if (sc < ts1) {
                        ts2 = ts1; ti2 = ti1;
                        if (sc < ts0) { ts1 = ts0; ti1 = ti0; ts0 = sc; ti0 = idx; }
                        else          { ts1 = sc;  ti1 = idx; }
                    } else { ts2 = sc; ti2 = idx; }
                }
            } else { /* not in top-4 */ }
            if (sc < ts3 && !(sc < ts2)) { ts3 = sc; ti3 = idx; }
        }
    }
    int gp = p0 + pr;
    *(int4*)(g_cand + (size_t)gp * 8 + ch * 4) = make_int4(ti0, ti1, ti2, ti3);
}

// =================== kernel 4: exact fp32 rescore + L4 residual ===========
__global__ void __launch_bounds__(256) finalize_k(const float* __restrict__ query,
                                                  const float* __restrict__ keys,
                                                  float* __restrict__ out) {
    extern __shared__ float qs[];              // [64][517]
    __shared__ float rn[64];
    int bh = blockIdx.x;
    int b = bh >> 6, h = bh & 63;
    const float* base = query + (size_t)b * (512 * 4096) + (size_t)h * 64;
    int t = threadIdx.x;
    if (t < 64) rn[t] = g_rnorm[bh * 64 + t];
    #pragma unroll
    for (int i = 0; i < 32; i++) {
        int idx = t + i * 256;
        int c = idx >> 4, w4 = idx & 15;
        float4 v = *(const float4*)(base + (size_t)c * 4096 + w4 * 4);
        qs[(w4 * 4 + 0) * 517 + c] = v.x;
        qs[(w4 * 4 + 1) * 517 + c] = v.y;
        qs[(w4 * 4 + 2) * 517 + c] = v.z;
        qs[(w4 * 4 + 3) * 517 + c] = v.w;
    }
    __syncthreads();

    int lane = t & 31, warp = t >> 5;
    #pragma unroll 1
    for (int it = 0; it < 8; it++) {
        int w = warp * 8 + it;
        int gp = bh * 64 + w;
        float r = rn[w];
        const float* q = qs + w * 517;
        float best = 3.4e38f; int bidx = 0x7fffffff;
        #pragma unroll 1
        for (int cd = 0; cd < 8; cd++) {
            int kidx = g_cand[(size_t)gp * 8 + cd];
            const float* kr = keys + (size_t)kidx * DDIM;
            float d = 0.f;
            #pragma unroll
            for (int j = 0; j < 16; j++)
                d = fmaf(q[lane + j * 32] * r, kr[lane + j * 32], d);
            #pragma unroll
            for (int o = 16; o; o >>= 1) d += __shfl_xor_sync(0xffffffffu, d, o);
            float sc = g_kq[kidx] - 2.f * d;
            if (sc < best || (sc == best && kidx < bidx)) { best = sc; bidx = kidx; }
        }
        const float* kr = keys + (size_t)bidx * DDIM;
        float hsum = 0.f;
        #pragma unroll
        for (int j = 0; j < 16; j++) {
            float diff = q[lane + j * 32] * r - kr[lane + j * 32];
            float d2 = diff * diff;
            hsum = fmaf(d2, d2, hsum);
        }
        #pragma unroll
        for (int o = 16; o; o >>= 1) hsum += __shfl_xor_sync(0xffffffffu, hsum, o);
        if (lane == 0) out[gp] = hsum;
    }
}

// =================== launch ===================
extern "C" void kernel_launch(void* const* d_in, const int* in_sizes, int n_in,
                              void* d_out, int out_size) {
    const float* query = (const float*)d_in[0];
    const float* keys  = (const float*)d_in[1];
    if (n_in >= 2 && in_sizes[0] == NKEYS * DDIM) {   // defensive input-order swap
        query = (const float*)d_in[1];
        keys  = (const float*)d_in[0];
    }
    float* out = (float*)d_out;

    cudaFuncSetAttribute(normalize_k, cudaFuncAttributeMaxDynamicSharedMemorySize, 512 * 68 * 4);
    cudaFuncSetAttribute(gemm_topk_k, cudaFuncAttributeMaxDynamicSharedMemorySize, G_SMEM);
    cudaFuncSetAttribute(finalize_k,  cudaFuncAttributeMaxDynamicSharedMemorySize, 64 * 517 * 4);

    prep_keys_k<<<MKEYS, 128>>>(keys);
    normalize_k<<<512, 256, 512 * 68 * 4>>>(query);
    gemm_topk_k<<<256, 256, G_SMEM>>>();
    finalize_k<<<512, 256, 64 * 517 * 4>>>(query, keys, out);
}

// round 12
// speedup vs baseline: 1.7277x; 1.7277x over previous
#include <cuda_runtime.h>
#include <cuda_bf16.h>
#include <cstdint>

#define NPIX   32768      // 8*64*64 pixels
#define DDIM   512
#define NKEYS  2000
#define MKEYS  2048       // padded key count

// ---------------- scratch (static device arrays; allocation-free) ----------
__device__ __align__(256) __nv_bfloat16 g_qb[(size_t)NPIX * DDIM];   // 32 MB normalized q, bf16
__device__ __align__(256) float         g_qf[(size_t)NPIX * DDIM];   // 64 MB normalized q, fp32
__device__ __align__(256) __nv_bfloat16 g_kb[(size_t)MKEYS * DDIM];  // 2 MB keys, bf16
__device__ __align__(256) float g_kq[MKEYS];                         // |k|^2 (pad = 3e38)
__device__ __align__(256) int   g_cand[(size_t)NPIX * 16];           // 16 candidates / pixel

// ---------------- helpers ----------------
__device__ __forceinline__ void mma_bf16(float* d, const uint32_t* a, uint32_t b0, uint32_t b1) {
    asm volatile(
        "mma.sync.aligned.m16n8k16.row.col.f32.bf16.bf16.f32 "
        "{%0,%1,%2,%3}, {%4,%5,%6,%7}, {%8,%9}, {%0,%1,%2,%3};\n"
        : "+f"(d[0]), "+f"(d[1]), "+f"(d[2]), "+f"(d[3])
        : "r"(a[0]), "r"(a[1]), "r"(a[2]), "r"(a[3]), "r"(b0), "r"(b1));
}

// sorted ascending top-2 insert (s[0] best)
__device__ __forceinline__ void ins2(float sc, int idx, float s[2], int id[2]) {
    if (sc < s[1]) {
        if (sc < s[0]) { s[1] = s[0]; id[1] = id[0]; s[0] = sc; id[0] = idx; }
        else           { s[1] = sc;  id[1] = idx; }
    }
}

// =================== kernel 1: key prep ===================
__global__ void prep_keys_k(const float* __restrict__ keys) {
    int j = blockIdx.x;          // 0..MKEYS-1
    int t = threadIdx.x;         // 128 threads
    float s = 0.f;
    if (j < NKEYS) {
        float4 v = ((const float4*)(keys + (size_t)j * DDIM))[t];
        s = v.x*v.x + v.y*v.y + v.z*v.z + v.w*v.w;
        __nv_bfloat162* dst = (__nv_bfloat162*)(g_kb + (size_t)j * DDIM);
        dst[2*t+0] = __floats2bfloat162_rn(v.x, v.y);
        dst[2*t+1] = __floats2bfloat162_rn(v.z, v.w);
    } else {
        // FIX (R11): exactly ONE row. float2 = 4 bf16, so 128 thr x dst[t]
        // covers the full 512-half row. The previous extra dst[t+128] store
        // wrote a second row; for j==2047 that ran 1KB past g_kb and
        // clobbered g_kq -> corrupted |k|^2 -> global argmin corruption
        // (the rel_err~0.45 in R7/R9/R10).
        ((float2*)(g_kb + (size_t)j * DDIM))[t] = make_float2(0.f, 0.f);
    }
    #pragma unroll
    for (int o = 16; o; o >>= 1) s += __shfl_xor_sync(0xffffffffu, s, o);
    __shared__ float ws[4];
    if ((t & 31) == 0) ws[t >> 5] = s;
    __syncthreads();
    if (t == 0) g_kq[j] = (j < NKEYS) ? (ws[0] + ws[1] + ws[2] + ws[3]) : 3.0e38f;
}

// =================== kernel 2: normalize + transpose (bf16 + fp32 out) =====
__global__ void __launch_bounds__(256) normalize_k(const float* __restrict__ query) {
    extern __shared__ float tile[];            // [512][68]
    __shared__ float part[16][16][4];
    __shared__ float rnw[64];

    int bh = blockIdx.x;                       // b*64 + h
    int b = bh >> 6, h = bh & 63;
    const float* base = query + (size_t)b * (512 * 4096) + (size_t)h * 64;
    int t = threadIdx.x;

    float a0 = 0.f, a1 = 0.f, a2 = 0.f, a3 = 0.f;
    #pragma unroll
    for (int i = 0; i < 32; i++) {
        int idx = t + i * 256;
        int c = idx >> 4, w4 = idx & 15;
        float4 v = *(const float4*)(base + (size_t)c * 4096 + w4 * 4);
        *(float4*)(tile + c * 68 + w4 * 4) = v;
        a0 = fmaf(v.x, v.x, a0); a1 = fmaf(v.y, v.y, a1);
        a2 = fmaf(v.z, v.z, a2); a3 = fmaf(v.w, v.w, a3);
    }
    part[t & 15][t >> 4][0] = a0; part[t & 15][t >> 4][1] = a1;
    part[t & 15][t >> 4][2] = a2; part[t & 15][t >> 4][3] = a3;
    __syncthreads();
    if (t < 64) {
        float s = 0.f;
        #pragma unroll
        for (int m = 0; m < 16; m++) s += part[t >> 2][m][t & 3];
        rnw[t] = 1.f / fmaxf(sqrtf(s), 1e-12f);
    }
    __syncthreads();

    int lane = t & 31, warp = t >> 5;
    #pragma unroll
    for (int it = 0; it < 8; it++) {
        int w = warp * 8 + it;
        float rn = rnw[w];
        __nv_bfloat162* dstb = (__nv_bfloat162*)(g_qb + (size_t)(bh * 64 + w) * DDIM);
        float* dstf = g_qf + (size_t)(bh * 64 + w) * DDIM;
        #pragma unroll
        for (int j = 0; j < 8; j++) {
            int c = j * 64 + lane * 2;
            float x = tile[c * 68 + w] * rn;
            float y = tile[(c + 1) * 68 + w] * rn;
            dstb[j * 32 + lane] = __floats2bfloat162_rn(x, y);
            *(float2*)(dstf + c) = make_float2(x, y);
        }
    }
}

// =================== kernel 3: HMMA GEMM + per-thread top-2 ===============
// 256 CTAs x 256 thr (8 warps, 4x2 warp grid; warp tile 32M x 64N).
// A resident [128 rows][520 halves] (130KB, R4-proven layout + loads);
// B register-prefetched (LDG regs -> STS, R4-proven addressing), double-
// buffered rows of 72 halves (2 x 18KB); |k|^2 in smem (8KB).
// Each thread keeps top-2 over ITS OWN disjoint 256-key column subset per
// pixel row slot and writes its OWN candidate slots: no merge logic at all.
// Union of the 8 owning threads' top-2 = 16 candidates/pixel, provably
// containing the bf16 argmin. finalize rescsores exactly in fp32.
#define SM_A   0
#define SM_B   133120          // 128*520*2
#define SM_KQ  (133120 + 36864)
#define SMEM_G (SM_KQ + 8192)

__global__ void __launch_bounds__(256, 1) gemm_hmma_k() {
    extern __shared__ unsigned char sm[];
    __nv_bfloat16* As = (__nv_bfloat16*)sm;
    float* kqs = (float*)(sm + SM_KQ);

    int t = threadIdx.x, lane = t & 31, warp = t >> 5;
    int wm = warp >> 1, wn = warp & 1;
    int p0 = blockIdx.x * 128;

    // ---- A fill: g_qb[p0..p0+127][0..511] -> rows of 520 halves (65 uint4) ----
    {
        const uint4* src = (const uint4*)(g_qb + (size_t)p0 * DDIM);
        uint4* dst = (uint4*)sm;
        #pragma unroll
        for (int i = 0; i < 32; i++) {
            int idx = t + i * 256;
            int r = idx >> 6, c = idx & 63;
            dst[r * 65 + c] = src[r * 64 + c];
        }
    }
    // ---- kq fill ----
    #pragma unroll
    for (int i = 0; i < 8; i++) kqs[t + i * 256] = g_kq[t + i * 256];

    // ---- per-thread B transfer coordinates (fixed across chunks) ----
    const uint4* kb4 = (const uint4*)g_kb;
    int br_[4], bc_[4];
    #pragma unroll
    for (int i = 0; i < 4; i++) {
        int idx = t + i * 256;
        br_[i] = idx >> 3;            // key row within 128-chunk
        bc_[i] = idx & 7;             // uint4 col within 8 (64 halves)
    }
    // ---- prefetch chunk g=0 (tile 0, kc 0) into registers ----
    uint4 breg[4];
    #pragma unroll
    for (int i = 0; i < 4; i++)
        breg[i] = kb4[(size_t)br_[i] * 64 + bc_[i]];

    // ---- R4-proven per-lane fragment coordinates ----
    int ar = wm * 32 + (lane >> 2);
    int ac = (lane & 3) * 2;
    int br = wn * 64 + (lane >> 2);
    int bc = (lane & 3) * 2;
    int colbase = wn * 64 + (lane & 3) * 2;

    // ---- per-thread top-2 state: 4 row-slots ----
    float t2s[4][2]; int t2i[4][2];
    #pragma unroll
    for (int s = 0; s < 4; s++) {
        t2s[s][0] = 1e30f; t2s[s][1] = 1e30f;
        t2i[s][0] = 0;     t2i[s][1] = 0;
    }

    float acc[2][8][4];

    #pragma unroll 1
    for (int g = 0; g < 128; g++) {            // g = tile*8 + kc  (16 tiles x 8 K-chunks)
        int tile = g >> 3, kc = g & 7;
        int buf = g & 1;

        // STS prefetched chunk g into buf (other buffer's last reads were
        // iteration g-2, separated by the barrier at g-1: single-barrier safe)
        {
            unsigned char* bb = sm + SM_B + buf * 18432;
            #pragma unroll
            for (int i = 0; i < 4; i++)
                *(uint4*)(bb + br_[i] * 144 + bc_[i] * 16) = breg[i];
        }
        // LDG chunk g+1 into registers (hidden under this chunk's MMA)
        if (g + 1 < 128) {
            int g1 = g + 1;
            int t1 = g1 >> 3, k1 = g1 & 7;
            #pragma unroll
            for (int i = 0; i < 4; i++)
                breg[i] = kb4[(size_t)(t1 * 128 + br_[i]) * 64 + k1 * 8 + bc_[i]];
        }
        __syncthreads();                       // B[g] visible CTA-wide (covers A on g=0)

        if (kc == 0) {
            #pragma unroll
            for (int mt = 0; mt < 2; mt++)
                #pragma unroll
                for (int nt = 0; nt < 8; nt++)
                    #pragma unroll
                    for (int k = 0; k < 4; k++) acc[mt][nt][k] = 0.f;
        }

        const __nv_bfloat16* Bs = (const __nv_bfloat16*)(sm + SM_B + buf * 18432);
        #pragma unroll
        for (int ks = 0; ks < 4; ks++) {
            uint32_t a[2][4];
            #pragma unroll
            for (int mt = 0; mt < 2; mt++) {
                int base = (ar + mt * 16) * 520 + kc * 64 + ks * 16 + ac;
                a[mt][0] = *(const uint32_t*)(As + base);
                a[mt][1] = *(const uint32_t*)(As + base + 8 * 520);
                a[mt][2] = *(const uint32_t*)(As + base + 8);
                a[mt][3] = *(const uint32_t*)(As + base + 8 * 520 + 8);
            }
            #pragma unroll
            for (int nt = 0; nt < 8; nt++) {
                int bb = (br + nt * 8) * 72 + ks * 16 + bc;
                uint32_t b0 = *(const uint32_t*)(Bs + bb);
                uint32_t b1 = *(const uint32_t*)(Bs + bb + 8);
                #pragma unroll
                for (int mt = 0; mt < 2; mt++)
                    mma_bf16(acc[mt][nt], a[mt], b0, b1);
            }
        }

        if (kc == 7) {                         // fold tile into per-thread top-2
            int kb = tile * 128 + colbase;
            #pragma unroll
            for (int mt = 0; mt < 2; mt++)
                #pragma unroll
                for (int nt = 0; nt < 8; nt++) {
                    int key = kb + nt * 8;
                    float q0 = kqs[key], q1 = kqs[key + 1];
                    ins2(q0 - 2.f * acc[mt][nt][0], key,     t2s[mt*2],   t2i[mt*2]);
                    ins2(q1 - 2.f * acc[mt][nt][1], key + 1, t2s[mt*2],   t2i[mt*2]);
                    ins2(q0 - 2.f * acc[mt][nt][2], key,     t2s[mt*2+1], t2i[mt*2+1]);
                    ins2(q1 - 2.f * acc[mt][nt][3], key + 1, t2s[mt*2+1], t2i[mt*2+1]);
                }
        }
    }

    // ---- writeout: every thread writes ITS OWN candidate slots ----
    // pixel row = wm*32 + mt*16 + half*8 + (lane>>2)  (slot s = mt*2+half)
    // candidate slot within pixel = (wn*4 + (lane&3)) * 2 + {0,1}
    #pragma unroll
    for (int s = 0; s < 4; s++) {
        int row  = wm * 32 + (s >> 1) * 16 + (s & 1) * 8 + (lane >> 2);
        int slot = (wn * 4 + (lane & 3)) * 2;
        *(int2*)(g_cand + (size_t)(p0 + row) * 16 + slot) =
            make_int2(t2i[s][0], t2i[s][1]);
    }
}

// =================== kernel 4: exact fp32 rescore (16 cands) + L4 =========
__global__ void __launch_bounds__(256) finalize16_k(const float* __restrict__ keys,
                                                    float* __restrict__ out) {
    int warp = threadIdx.x >> 5, lane = threadIdx.x & 31;
    int p = blockIdx.x * 8 + warp;
    const float* q = g_qf + (size_t)p * DDIM;
    float qr[16];
    #pragma unroll
    for (int j = 0; j < 16; j++) qr[j] = q[j * 32 + lane];

    float best = 3.4e38f; int bidx = 0x7fffffff;
    #pragma unroll 1
    for (int c = 0; c < 16; c++) {
        int k = g_cand[(size_t)p * 16 + c];
        const float* kr = keys + (size_t)k * DDIM;
        float d = 0.f;
        #pragma unroll
        for (int j = 0; j < 16; j++) d = fmaf(qr[j], kr[j * 32 + lane], d);
        #pragma unroll
        for (int o = 16; o; o >>= 1) d += __shfl_xor_sync(0xffffffffu, d, o);
        float sc = g_kq[k] - 2.f * d;
        if (sc < best || (sc == best && k < bidx)) { best = sc; bidx = k; }
    }
    const float* kr = keys + (size_t)bidx * DDIM;
    float hs = 0.f;
    #pragma unroll
    for (int j = 0; j < 16; j++) {
        float diff = qr[j] - kr[j * 32 + lane];
        float d2 = diff * diff;
        hs = fmaf(d2, d2, hs);
    }
    #pragma unroll
    for (int o = 16; o; o >>= 1) hs += __shfl_xor_sync(0xffffffffu, hs, o);
    if (lane == 0) out[p] = hs;
}

// =================== launch ===================
extern "C" void kernel_launch(void* const* d_in, const int* in_sizes, int n_in,
                              void* d_out, int out_size) {
    const float* query = (const float*)d_in[0];
    const float* keys  = (const float*)d_in[1];
    if (n_in >= 2 && in_sizes[0] == NKEYS * DDIM) {   // defensive input-order swap
        query = (const float*)d_in[1];
        keys  = (const float*)d_in[0];
    }
    float* out = (float*)d_out;

    cudaFuncSetAttribute(normalize_k,  cudaFuncAttributeMaxDynamicSharedMemorySize, 512 * 68 * 4);
    cudaFuncSetAttribute(gemm_hmma_k,  cudaFuncAttributeMaxDynamicSharedMemorySize, SMEM_G);

    prep_keys_k<<<MKEYS, 128>>>(keys);
    normalize_k<<<512, 256, 512 * 68 * 4>>>(query);
    gemm_hmma_k<<<256, 256, SMEM_G>>>();
    finalize16_k<<<NPIX / 8, 256>>>(keys, out);
}